// round 12
// baseline (speedup 1.0000x reference)
#include <cuda_runtime.h>
#include <cuda_fp16.h>

// ForwardWarp: forward splatting with Gaussian softmax weights.
// img, counts: (8,1,720,1280) f32; flo: (8,2,720,1280) f32 (ch0 = y shifts W, ch1 = x shifts H)
// out: [0:S) = img_warp / (one_warp + eps), [S:2S) = one_warp
//
// Splat (validated R8/R11, at the RED-lane LSU floor): one branchless
// red.global.add.noftz.v4.f16x2 per pixel into 4 parity copies (pr=ix1&1, pc=iy1&1),
// rowpair-interleaved layout. Scratch chunk-shared (29.6MB, L2-resident).
// Normalize: SINGLE-COLUMN sweep. Thread owns ONE column and 4 pair-rows; marries
// the row-straddling pr=1 words via a register carry -> ~1.0x scratch read; zero-stores
// exactly the words it consumed (word-disjoint -> race-free, no memset node).
// Single-column split doubles blocks (900) vs R11 (450) with byte-identical traffic:
// pure occupancy/latency win. Unread pad words are never zeroed (harmless; never read).
//
// Cell (row,col) addressing inside a copy with column-parity pcsel:
//   word = 2*col + 2*pcsel + dr, pair row P: pr=0 -> rows {2P, 2P+1} (dr=0/1),
//   pr=1 -> rows {2P-1, 2P} (dr=0/1).

static constexpr int N_ = 8;
static constexpr int H_ = 720;
static constexpr int W_ = 1280;
static constexpr int S_ = N_ * H_ * W_;     // 7,372,800
static constexpr float EPS_ = 1e-6f;

static constexpr int CHUNKS_ = 4;           // 2 images per chunk
static constexpr int PC_ = S_ / CHUNKS_;    // 1,843,200 pixels per chunk

static constexpr int NP_ = 361;             // pair-rows per copy per image (incl. pads)
static constexpr int WPAD_ = 2564;          // words per pair-row (16B multiple)
static constexpr int NPW_ = NP_ * WPAD_;    // words per copy per image
static constexpr int SCR_WORDS_ = 8 * NPW_; // 4 copies x 2 images = 29.6MB

__device__ __align__(16) unsigned int g_S[SCR_WORDS_];  // BSS zero; fused zero-stores restore

__device__ __forceinline__ void red_v4h2(unsigned int* p, unsigned int s0, unsigned int s1,
                                         unsigned int s2, unsigned int s3) {
    asm volatile("red.global.add.noftz.v4.f16x2 [%0], {%1, %2, %3, %4};"
                 :: "l"(p), "r"(s0), "r"(s1), "r"(s2), "r"(s3) : "memory");
}
__device__ __forceinline__ unsigned int pack_h2(float a, float b) {
    __half2 h = __float22half2_rn(make_float2(a, b));
    return *reinterpret_cast<unsigned int*>(&h);
}
__device__ __forceinline__ float2 unpack_h2(unsigned int u) {
    return __half22float2(*reinterpret_cast<__half2*>(&u));
}

__global__ void __launch_bounds__(256) splat_kernel(
    const float* __restrict__ img,
    const float* __restrict__ counts,
    const float* __restrict__ flo,
    int chunk)
{
    int idx = chunk * PC_ + blockIdx.x * blockDim.x + threadIdx.x;

    int w  = idx % W_;
    int hw = idx / W_;
    int h  = hw % H_;
    int n  = hw / H_;
    int ni = n & 1;                 // image within chunk

    int flo_base = ((n * 2) * H_ + h) * W_ + w;
    float y = __ldcs(flo + flo_base);
    float x = __ldcs(flo + flo_base + H_ * W_);

    float im = __ldcs(img + idx);
    float c  = __ldcs(counts + idx);

    float x1 = floorf(x);
    float y1 = floorf(y);
    float fx = x - x1;
    float fy = y - y1;
    float gx = fx - 1.0f;
    float gy = fy - 1.0f;

    float dx1 = fx * fx, dx2 = gx * gx;
    float dy1 = fy * fy, dy2 = gy * gy;

    float w11 = __expf(-(dx1 + dy1));   // row ix1, col iy1
    float w12 = __expf(-(dx1 + dy2));   // row ix1, col iy2
    float w21 = __expf(-(dx2 + dy1));   // row ix2, col iy1
    float w22 = __expf(-(dx2 + dy2));   // row ix2, col iy2
    float inv = 1.0f / (w11 + w12 + w21 + w22);
    float cinv = c * inv;

    int ix1 = (int)x1 + h;
    int iy1 = (int)y1 + w;

    if (ix1 < -1 || ix1 > H_ - 1 || iy1 < -1 || iy1 > W_ - 1) return;

    int pr = ix1 & 1;                     // (-1 & 1) == 1
    int pc = iy1 & 1;
    int P  = (ix1 + pr) >> 1;
    int wv = 2 * iy1 + 2 * pc;

    unsigned int* p = g_S + (((pr * 2 + pc) * 2 + ni) * NP_ + P) * WPAD_ + wv;

    // word order in footprint: [ (r1,c1), (r2,c1), (r1,c2), (r2,c2) ]
    red_v4h2(p,
             pack_h2(im * (w11 * cinv), w11 * cinv),
             pack_h2(im * (w21 * cinv), w21 * cinv),
             pack_h2(im * (w12 * cinv), w12 * cinv),
             pack_h2(im * (w22 * cinv), w22 * cinv));
}

// Single-column sweep. Thread owns column c, image ni, pair-rows [p0, p0+4).
// Step p finalizes output rows {2p, 2p+1}:
//   row 2p:   c00 pair p .x + c01 pair p .x + c10 pair p .y (carried) + c11 pair p .y (carried)
//   row 2p+1: c00 pair p .y + c01 pair p .y + c10 pair p+1 .x + c11 pair p+1 .x
// Boundary pr=1 pairs are shared with neighbor segments; each segment zero-stores
// ONLY the words it consumed (disjoint) -> race-free.
static constexpr int SEGS_ = 90;            // 360 pairs / 4 per segment

__global__ void __launch_bounds__(256) normalize_kernel(float* __restrict__ out, int chunk)
{
    int t = blockIdx.x * blockDim.x + threadIdx.x;  // 0 .. 230399 per chunk
    int c    = t % W_;              // column 0..1279
    int rest = t / W_;
    int seg  = rest % SEGS_;        // 0..89
    int ni   = rest / SEGS_;        // 0..1
    int n    = chunk * 2 + ni;
    int p0   = seg * 4;

    int q0 = 2 * c;                 // word base in pc=0 copies
    int q1 = 2 * c + 2;             // word base in pc=1 copies

    unsigned int* c00 = g_S + (0 + ni) * NPW_;
    unsigned int* c01 = g_S + (2 + ni) * NPW_;
    unsigned int* c10 = g_S + (4 + ni) * NPW_;
    unsigned int* c11 = g_S + (6 + ni) * NPW_;

    // prologue: carried pr=1 pair p0 (consume only .y words = row 2*p0)
    int rpro = p0 * WPAD_;
    uint2 A = *reinterpret_cast<uint2*>(c10 + rpro + q0);
    uint2 F = *reinterpret_cast<uint2*>(c11 + rpro + q1);

    const uint2 z2 = make_uint2(0u, 0u);

    #pragma unroll
    for (int i = 0; i < 4; i++) {
        int p   = p0 + i;
        int rp  = p * WPAD_;
        int rp1 = rp + WPAD_;

        uint2 V  = *reinterpret_cast<uint2*>(c00 + rp + q0);
        uint2 U  = *reinterpret_cast<uint2*>(c01 + rp + q1);
        uint2 A2 = *reinterpret_cast<uint2*>(c10 + rp1 + q0);
        uint2 F2 = *reinterpret_cast<uint2*>(c11 + rp1 + q1);

        float2 a0 = unpack_h2(V.x), a1 = unpack_h2(U.x), a2 = unpack_h2(A.y),  a3 = unpack_h2(F.y);
        float2 b0 = unpack_h2(V.y), b1 = unpack_h2(U.y), b2 = unpack_h2(A2.x), b3 = unpack_h2(F2.x);

        float numA = (a0.x + a1.x) + (a2.x + a3.x);
        float denA = (a0.y + a1.y) + (a2.y + a3.y);
        float numB = (b0.x + b1.x) + (b2.x + b3.x);
        float denB = (b0.y + b1.y) + (b2.y + b3.y);

        int o0 = ((n * H_) + 2 * p) * W_ + c;     // row 2p
        int o1 = o0 + W_;                          // row 2p+1
        out[o0]      = numA / (denA + EPS_);
        out[o1]      = numB / (denB + EPS_);
        out[S_ + o0] = denA;
        out[S_ + o1] = denB;

        // zero-restore pair p
        *reinterpret_cast<uint2*>(c00 + rp + q0) = z2;
        *reinterpret_cast<uint2*>(c01 + rp + q1) = z2;
        if (i == 0) {
            // prologue pair: consumed only .y words
            c10[rp + q0 + 1] = 0u;
            c11[rp + q1 + 1] = 0u;
        } else {
            *reinterpret_cast<uint2*>(c10 + rp + q0) = z2;
            *reinterpret_cast<uint2*>(c11 + rp + q1) = z2;
        }

        A = A2; F = F2;
    }

    // epilogue: pair p0+4 — consumed only .x words
    int re = (p0 + 4) * WPAD_;
    c10[re + q0] = 0u;
    c11[re + q1] = 0u;
}

extern "C" void kernel_launch(void* const* d_in, const int* in_sizes, int n_in,
                              void* d_out, int out_size)
{
    const float* img    = (const float*)d_in[0];
    const float* counts = (const float*)d_in[1];
    const float* flo    = (const float*)d_in[2];
    float* out = (float*)d_out;

    int splat_blocks = PC_ / 256;                    // 7200
    int norm_blocks  = W_ * SEGS_ * 2 / 256;         // 900

    for (int chunk = 0; chunk < CHUNKS_; chunk++) {
        splat_kernel<<<splat_blocks, 256>>>(img, counts, flo, chunk);
        normalize_kernel<<<norm_blocks, 256>>>(out, chunk);
    }
}